// round 7
// baseline (speedup 1.0000x reference)
#include <cuda_runtime.h>
#include <cuda_fp16.h>
#include <mma.h>

using namespace nvcuda;

// Problem dims
#define BATCH 512
#define TSEQ  256
#define CEMB  384
#define HS    64
#define MTOT  (BATCH * TSEQ)   // 131072

// ---------------- scratch (device globals: allocation-guard safe) -------------
// Stored as HALF: rounding moved upstream (identical to converting at use site).
// g_q is pre-scaled by 1/sqrt(384).
__device__ __half g_q[MTOT * HS];
__device__ __half g_k[MTOT * HS];
__device__ __half g_v[MTOT * HS];

struct alignas(16) H8 { __half2 h[4]; };

__device__ __forceinline__ H8 pack8(float4 a, float4 b) {
    H8 r;
    r.h[0] = __floats2half2_rn(a.x, a.y);
    r.h[1] = __floats2half2_rn(a.z, a.w);
    r.h[2] = __floats2half2_rn(b.x, b.y);
    r.h[3] = __floats2half2_rn(b.z, b.w);
    return r;
}

// =============================================================================
// Kernel 1: QKV projection  qkv = x @ w   (M=131072, N=192, K=384), fp16 MMA.
// 256 threads, CTA tile 64x192, BK=32. 8 warps (2x4), warp tile 32x48.
// Double-buffered half smem + register prefetch; fp32 accumulate.
// Epilogue: fragments staged through per-warp smem, converted to half,
// written to g_q (scaled) / g_k / g_v.
// =============================================================================
#define PBM 64
#define PBN 192
#define PBK 32
#define A_LDH 40     // halves (80B stride)
#define B_LDH 200    // halves (400B stride)
#define KTILES (CEMB / PBK)   // 12

__global__ __launch_bounds__(256, 2)
void qkv_proj_kernel(const float* __restrict__ x, const float* __restrict__ w)
{
    __shared__ __half As[2][PBM * A_LDH];   // 10240B
    __shared__ __half Bs[2][PBK * B_LDH];   // 25600B
    __shared__ float  stg[8][16 * 20];      // per-warp epilogue staging, 10240B

    const int tid    = threadIdx.x;
    const int wid    = tid >> 5;
    const int lane   = tid & 31;
    const int m_base = blockIdx.x * PBM;

    const int wm = (wid & 1) * 32;       // 2 warp-rows
    const int wn = (wid >> 1) * 48;      // 4 warp-cols

    const int a_row = tid >> 2;
    const int a_c0  = (tid & 3) * 8;
    const int b_row = tid >> 3;
    const int b_c0  = (tid & 7) * 24;

    const float* xA = x + (size_t)(m_base + a_row) * CEMB + a_c0;
    const float* wB = w + (size_t)b_row * PBN + b_c0;

    float4 a_reg[2];
    float4 b_reg[6];

    // prologue: tile 0
    #pragma unroll
    for (int i = 0; i < 2; i++) a_reg[i] = *(const float4*)(xA + i * 4);
    #pragma unroll
    for (int i = 0; i < 6; i++) b_reg[i] = *(const float4*)(wB + i * 4);

    *(H8*)(As[0] + a_row * A_LDH + a_c0) = pack8(a_reg[0], a_reg[1]);
    #pragma unroll
    for (int i = 0; i < 3; i++)
        *(H8*)(Bs[0] + b_row * B_LDH + b_c0 + i * 8) = pack8(b_reg[2 * i], b_reg[2 * i + 1]);
    __syncthreads();

    wmma::fragment<wmma::accumulator, 16, 16, 16, float> acc[2][3];
    #pragma unroll
    for (int i = 0; i < 2; i++)
        #pragma unroll
        for (int j = 0; j < 3; j++)
            wmma::fill_fragment(acc[i][j], 0.0f);

    for (int t = 0; t < KTILES; t++) {
        if (t + 1 < KTILES) {
            const int k0 = (t + 1) * PBK;
            #pragma unroll
            for (int i = 0; i < 2; i++) a_reg[i] = *(const float4*)(xA + k0 + i * 4);
            const float* wn2 = wB + (size_t)k0 * PBN;
            #pragma unroll
            for (int i = 0; i < 6; i++) b_reg[i] = *(const float4*)(wn2 + i * 4);
        }

        const __half* Ac = As[t & 1];
        const __half* Bc = Bs[t & 1];
        #pragma unroll
        for (int kk = 0; kk < PBK; kk += 16) {
            wmma::fragment<wmma::matrix_a, 16, 16, 16, __half, wmma::row_major> a[2];
            wmma::fragment<wmma::matrix_b, 16, 16, 16, __half, wmma::row_major> b[3];
            #pragma unroll
            for (int i = 0; i < 2; i++)
                wmma::load_matrix_sync(a[i], Ac + (wm + i * 16) * A_LDH + kk, A_LDH);
            #pragma unroll
            for (int j = 0; j < 3; j++)
                wmma::load_matrix_sync(b[j], Bc + kk * B_LDH + wn + j * 16, B_LDH);
            #pragma unroll
            for (int i = 0; i < 2; i++)
                #pragma unroll
                for (int j = 0; j < 3; j++)
                    wmma::mma_sync(acc[i][j], a[i], b[j], acc[i][j]);
        }

        if (t + 1 < KTILES) {
            __half* An = As[(t + 1) & 1];
            __half* Bn = Bs[(t + 1) & 1];
            __syncthreads();
            *(H8*)(An + a_row * A_LDH + a_c0) = pack8(a_reg[0], a_reg[1]);
            #pragma unroll
            for (int i = 0; i < 3; i++)
                *(H8*)(Bn + b_row * B_LDH + b_c0 + i * 8) = pack8(b_reg[2 * i], b_reg[2 * i + 1]);
            __syncthreads();
        }
    }

    // ---- epilogue: stage each fragment in smem, convert to half, STG ----
    const float scale = rsqrtf((float)CEMB);   // folded into q
    const int r  = lane >> 1;
    const int c0 = (lane & 1) * 8;
    #pragma unroll
    for (int i = 0; i < 2; i++) {
        #pragma unroll
        for (int j = 0; j < 3; j++) {
            const int col   = wn + j * 16;
            const int slice = col >> 6;          // 0,1,2 -> q,k,v
            const int lcol  = col & 63;
            __half* dst = (slice == 0) ? g_q : ((slice == 1) ? g_k : g_v);
            if (slice == 0) {
                #pragma unroll
                for (int e = 0; e < acc[i][j].num_elements; e++)
                    acc[i][j].x[e] *= scale;
            }
            __syncwarp();
            wmma::store_matrix_sync(stg[wid], acc[i][j], 20, wmma::mem_row_major);
            __syncwarp();
            float4 f0 = *(float4*)(stg[wid] + r * 20 + c0);
            float4 f1 = *(float4*)(stg[wid] + r * 20 + c0 + 4);
            *(H8*)(dst + (size_t)(m_base + wm + i * 16 + r) * HS + lcol + c0) = pack8(f0, f1);
        }
    }
}

// =============================================================================
// Kernel 2: fused causal attention, fp16 MMA, half inputs. One CTA per
// (batch, 64-row query tile), grid (4, 512), 256 threads.
// K/V streamed in 64x64 half tiles, DOUBLE-BUFFERED (one barrier per tile).
// S accumulated fp32 in smem; softmax one register pass per row; normalized
// half P written in place over S; PV accumulators persist in registers.
// =============================================================================
#define KV_LDH 72     // halves (144B stride)
#define S_LDF  264    // floats
#define P_LDH  528    // halves (same bytes)

#define QB_BYTES  (64 * KV_LDH * 2)       // 9216
#define KVB_BYTES (2 * 64 * KV_LDH * 2)   // 18432 (two buffers)
#define SB_BYTES  (64 * S_LDF * 4)        // 67584
#define ATT_SMEM_BYTES (QB_BYTES + KVB_BYTES + SB_BYTES)   // 95232

__global__ __launch_bounds__(256, 2)
void attn_kernel(float* __restrict__ out)
{
    extern __shared__ char smraw[];
    __half* Qs  = (__half*)smraw;
    __half* KV0 = (__half*)(smraw + QB_BYTES);
    __half* KV1 = KV0 + 64 * KV_LDH;
    float*  Ss  = (float*)(smraw + QB_BYTES + KVB_BYTES);
    __half* Ps  = (__half*)Ss;                 // alias: P overwrites dead S

    const int tid  = threadIdx.x;
    const int wid  = tid >> 5;
    const int lane = tid & 31;
    const int qt   = blockIdx.x;
    const int b    = blockIdx.y;

    const __half* Qg = g_q + (size_t)b * TSEQ * HS + (size_t)qt * 64 * HS;
    const __half* Kg = g_k + (size_t)b * TSEQ * HS;
    const __half* Vg = g_v + (size_t)b * TSEQ * HS;
    float*        Og = out + (size_t)b * TSEQ * HS + (size_t)qt * 64 * HS;

    const int wm = wid & 3;            // warp's m tile
    const int wn = wid >> 2;           // warp's first n tile; second = wn+2

    const int t_row = tid >> 2;        // 0..63
    const int t_c0  = (tid & 3) * 16;  // 16 halves per thread

    H8 kv_reg[2];

    // ---- prologue: copy Q (pre-scaled, half) + K tile 0 ----
    {
        H8 q0 = *(const H8*)(Qg + t_row * HS + t_c0);
        H8 q1 = *(const H8*)(Qg + t_row * HS + t_c0 + 8);
        kv_reg[0] = *(const H8*)(Kg + t_row * HS + t_c0);
        kv_reg[1] = *(const H8*)(Kg + t_row * HS + t_c0 + 8);
        *(H8*)(Qs + t_row * KV_LDH + t_c0)     = q0;
        *(H8*)(Qs + t_row * KV_LDH + t_c0 + 8) = q1;
        *(H8*)(KV0 + t_row * KV_LDH + t_c0)     = kv_reg[0];
        *(H8*)(KV0 + t_row * KV_LDH + t_c0 + 8) = kv_reg[1];
    }
    __syncthreads();

    // ---- S = Q K^T, double-buffered K tiles, one barrier per tile ----
    for (int kt = 0; kt <= qt; kt++) {
        __half* cur = (kt & 1) ? KV1 : KV0;
        __half* nxt = (kt & 1) ? KV0 : KV1;
        if (kt < qt) {
            const __half* src = Kg + ((kt + 1) * 64 + t_row) * HS + t_c0;
            kv_reg[0] = *(const H8*)(src);
            kv_reg[1] = *(const H8*)(src + 8);
        }

        wmma::fragment<wmma::accumulator, 16, 16, 16, float> sacc[2];
        wmma::fill_fragment(sacc[0], 0.0f);
        wmma::fill_fragment(sacc[1], 0.0f);
        #pragma unroll
        for (int kk = 0; kk < HS; kk += 16) {
            wmma::fragment<wmma::matrix_a, 16, 16, 16, __half, wmma::row_major> a;
            wmma::fragment<wmma::matrix_b, 16, 16, 16, __half, wmma::col_major> kb[2];
            wmma::load_matrix_sync(a, Qs + wm * 16 * KV_LDH + kk, KV_LDH);
            wmma::load_matrix_sync(kb[0], cur + wn * 16 * KV_LDH + kk, KV_LDH);
            wmma::load_matrix_sync(kb[1], cur + (wn + 2) * 16 * KV_LDH + kk, KV_LDH);
            wmma::mma_sync(sacc[0], a, kb[0], sacc[0]);
            wmma::mma_sync(sacc[1], a, kb[1], sacc[1]);
        }
        wmma::store_matrix_sync(Ss + wm * 16 * S_LDF + kt * 64 + wn * 16,
                                sacc[0], S_LDF, wmma::mem_row_major);
        wmma::store_matrix_sync(Ss + wm * 16 * S_LDF + kt * 64 + (wn + 2) * 16,
                                sacc[1], S_LDF, wmma::mem_row_major);

        if (kt < qt) {
            // nxt buffer was last read two iterations ago; safe after the
            // barrier that ended iteration kt-1.
            *(H8*)(nxt + t_row * KV_LDH + t_c0)     = kv_reg[0];
            *(H8*)(nxt + t_row * KV_LDH + t_c0 + 8) = kv_reg[1];
        }
        __syncthreads();
    }

    // ---- V tile 0: load + store into KV0 (all KV reads finished above) ----
    kv_reg[0] = *(const H8*)(Vg + t_row * HS + t_c0);
    kv_reg[1] = *(const H8*)(Vg + t_row * HS + t_c0 + 8);
    *(H8*)(KV0 + t_row * KV_LDH + t_c0)     = kv_reg[0];
    *(H8*)(KV0 + t_row * KV_LDH + t_c0 + 8) = kv_reg[1];

    // ---- softmax: one register pass per row; normalized half P in place ----
    for (int row = wid; row < 64; row += 8) {
        const int nv = qt * 64 + row + 1;          // causal valid length
        float*  Sr = Ss + row * S_LDF;
        __half* Pr = Ps + row * P_LDH;

        float ex[8];
        float sum = 0.0f;
        #pragma unroll
        for (int j = 0; j < 4; j++) {
            if (j <= qt) {
                const int c = lane * 2 + j * 64;
                float2 v = *(float2*)(Sr + c);
                float e0 = (c     < nv) ? __expf(v.x) : 0.0f;
                float e1 = (c + 1 < nv) ? __expf(v.y) : 0.0f;
                ex[2 * j] = e0; ex[2 * j + 1] = e1;
                sum += e0 + e1;
            }
        }
        #pragma unroll
        for (int off = 16; off; off >>= 1) sum += __shfl_xor_sync(0xffffffffu, sum, off);
        const float inv = 1.0f / sum;

        __syncwarp();   // all S reads for this row complete before P overwrites
        #pragma unroll
        for (int j = 0; j < 4; j++) {
            if (j <= qt) {
                const int c = lane * 2 + j * 64;
                *(__half2*)(Pr + c) = __floats2half2_rn(ex[2 * j] * inv, ex[2 * j + 1] * inv);
            }
        }
    }
    __syncthreads();

    // ---- O = P V, double-buffered V tiles; accumulators in registers ----
    wmma::fragment<wmma::accumulator, 16, 16, 16, float> oacc[2];
    wmma::fill_fragment(oacc[0], 0.0f);
    wmma::fill_fragment(oacc[1], 0.0f);

    for (int kt = 0; kt <= qt; kt++) {
        __half* cur = (kt & 1) ? KV1 : KV0;
        __half* nxt = (kt & 1) ? KV0 : KV1;
        if (kt < qt) {
            const __half* src = Vg + ((kt + 1) * 64 + t_row) * HS + t_c0;
            kv_reg[0] = *(const H8*)(src);
            kv_reg[1] = *(const H8*)(src + 8);
        }

        #pragma unroll
        for (int kk = 0; kk < 64; kk += 16) {
            wmma::fragment<wmma::matrix_a, 16, 16, 16, __half, wmma::row_major> p;
            wmma::fragment<wmma::matrix_b, 16, 16, 16, __half, wmma::row_major> vb[2];
            wmma::load_matrix_sync(p, Ps + wm * 16 * P_LDH + kt * 64 + kk, P_LDH);
            wmma::load_matrix_sync(vb[0], cur + kk * KV_LDH + wn * 16, KV_LDH);
            wmma::load_matrix_sync(vb[1], cur + kk * KV_LDH + (wn + 2) * 16, KV_LDH);
            wmma::mma_sync(oacc[0], p, vb[0], oacc[0]);
            wmma::mma_sync(oacc[1], p, vb[1], oacc[1]);
        }

        if (kt < qt) {
            *(H8*)(nxt + t_row * KV_LDH + t_c0)     = kv_reg[0];
            *(H8*)(nxt + t_row * KV_LDH + t_c0 + 8) = kv_reg[1];
        }
        __syncthreads();
    }

    wmma::store_matrix_sync(Og + (wm * 16) * HS + wn * 16, oacc[0], HS,
                            wmma::mem_row_major);
    wmma::store_matrix_sync(Og + (wm * 16) * HS + (wn + 2) * 16, oacc[1], HS,
                            wmma::mem_row_major);
}

// =============================================================================
extern "C" void kernel_launch(void* const* d_in, const int* in_sizes, int n_in,
                              void* d_out, int out_size)
{
    const float* x = (const float*)d_in[0];     // [512,256,384]
    const float* w = (const float*)d_in[1];     // [384,192]
    float* out = (float*)d_out;                 // [512,256,64]

    (void)in_sizes; (void)n_in; (void)out_size;

    static bool attr_set = false;
    if (!attr_set) {
        cudaFuncSetAttribute(attn_kernel, cudaFuncAttributeMaxDynamicSharedMemorySize,
                             ATT_SMEM_BYTES);
        attr_set = true;
    }

    qkv_proj_kernel<<<MTOT / PBM, 256>>>(x, w);
    attn_kernel<<<dim3(4, BATCH), 256, ATT_SMEM_BYTES>>>(out);
}

// round 11
// speedup vs baseline: 1.2084x; 1.2084x over previous
#include <cuda_runtime.h>
#include <cuda_fp16.h>
#include <mma.h>
#include <cstdint>

using namespace nvcuda;

// Problem dims
#define BATCH 512
#define TSEQ  256
#define CEMB  384
#define HS    64
#define MTOT  (BATCH * TSEQ)   // 131072

// ---------------- scratch (device globals: allocation-guard safe) -------------
__device__ float g_q[MTOT * HS];
__device__ float g_k[MTOT * HS];
__device__ float g_v[MTOT * HS];

struct alignas(16) H8 { __half2 h[4]; };

__device__ __forceinline__ H8 pack8(float4 a, float4 b) {
    H8 r;
    r.h[0] = __floats2half2_rn(a.x, a.y);
    r.h[1] = __floats2half2_rn(a.z, a.w);
    r.h[2] = __floats2half2_rn(b.x, b.y);
    r.h[3] = __floats2half2_rn(b.z, b.w);
    return r;
}

__device__ __forceinline__ uint32_t h2u(__half2 h) {
    return *reinterpret_cast<uint32_t*>(&h);
}

// ---------------- raw PTX: ldmatrix + mma.m16n8k16 ----------------
#define LDM_X4(r0, r1, r2, r3, a) \
    asm volatile("ldmatrix.sync.aligned.m8n8.x4.shared.b16 {%0,%1,%2,%3}, [%4];" \
                 : "=r"(r0), "=r"(r1), "=r"(r2), "=r"(r3) : "r"(a))
#define LDM_X2(r0, r1, a) \
    asm volatile("ldmatrix.sync.aligned.m8n8.x2.shared.b16 {%0,%1}, [%2];" \
                 : "=r"(r0), "=r"(r1) : "r"(a))
#define LDM_X2T(r0, r1, a) \
    asm volatile("ldmatrix.sync.aligned.m8n8.x2.trans.shared.b16 {%0,%1}, [%2];" \
                 : "=r"(r0), "=r"(r1) : "r"(a))

__device__ __forceinline__ void mma16816(float* c, uint32_t a0, uint32_t a1,
                                         uint32_t a2, uint32_t a3,
                                         uint32_t b0, uint32_t b1) {
    asm volatile(
        "mma.sync.aligned.m16n8k16.row.col.f32.f16.f16.f32 "
        "{%0,%1,%2,%3}, {%4,%5,%6,%7}, {%8,%9}, {%0,%1,%2,%3};"
        : "+f"(c[0]), "+f"(c[1]), "+f"(c[2]), "+f"(c[3])
        : "r"(a0), "r"(a1), "r"(a2), "r"(a3), "r"(b0), "r"(b1));
}

// =============================================================================
// Kernel 1: QKV projection (R6 version, verbatim). fp16 MMA, fp32 outputs.
// =============================================================================
#define PBM 64
#define PBN 192
#define PBK 32
#define A_LDH 40
#define B_LDH 200
#define KTILES (CEMB / PBK)   // 12

__global__ __launch_bounds__(256, 2)
void qkv_proj_kernel(const float* __restrict__ x, const float* __restrict__ w)
{
    __shared__ __half As[2][PBM * A_LDH];
    __shared__ __half Bs[2][PBK * B_LDH];

    const int tid    = threadIdx.x;
    const int wid    = tid >> 5;
    const int m_base = blockIdx.x * PBM;

    const int wm = (wid & 1) * 32;
    const int wn = (wid >> 1) * 48;

    const int a_row = tid >> 2;
    const int a_c0  = (tid & 3) * 8;
    const int b_row = tid >> 3;
    const int b_c0  = (tid & 7) * 24;

    const float* xA = x + (size_t)(m_base + a_row) * CEMB + a_c0;
    const float* wB = w + (size_t)b_row * PBN + b_c0;

    float4 a_reg[2];
    float4 b_reg[6];

    #pragma unroll
    for (int i = 0; i < 2; i++) a_reg[i] = *(const float4*)(xA + i * 4);
    #pragma unroll
    for (int i = 0; i < 6; i++) b_reg[i] = *(const float4*)(wB + i * 4);

    *(H8*)(As[0] + a_row * A_LDH + a_c0) = pack8(a_reg[0], a_reg[1]);
    #pragma unroll
    for (int i = 0; i < 3; i++)
        *(H8*)(Bs[0] + b_row * B_LDH + b_c0 + i * 8) = pack8(b_reg[2 * i], b_reg[2 * i + 1]);
    __syncthreads();

    wmma::fragment<wmma::accumulator, 16, 16, 16, float> acc[2][3];
    #pragma unroll
    for (int i = 0; i < 2; i++)
        #pragma unroll
        for (int j = 0; j < 3; j++)
            wmma::fill_fragment(acc[i][j], 0.0f);

    for (int t = 0; t < KTILES; t++) {
        if (t + 1 < KTILES) {
            const int k0 = (t + 1) * PBK;
            #pragma unroll
            for (int i = 0; i < 2; i++) a_reg[i] = *(const float4*)(xA + k0 + i * 4);
            const float* wn2 = wB + (size_t)k0 * PBN;
            #pragma unroll
            for (int i = 0; i < 6; i++) b_reg[i] = *(const float4*)(wn2 + i * 4);
        }

        const __half* Ac = As[t & 1];
        const __half* Bc = Bs[t & 1];
        #pragma unroll
        for (int kk = 0; kk < PBK; kk += 16) {
            wmma::fragment<wmma::matrix_a, 16, 16, 16, __half, wmma::row_major> a[2];
            wmma::fragment<wmma::matrix_b, 16, 16, 16, __half, wmma::row_major> b[3];
            #pragma unroll
            for (int i = 0; i < 2; i++)
                wmma::load_matrix_sync(a[i], Ac + (wm + i * 16) * A_LDH + kk, A_LDH);
            #pragma unroll
            for (int j = 0; j < 3; j++)
                wmma::load_matrix_sync(b[j], Bc + kk * B_LDH + wn + j * 16, B_LDH);
            #pragma unroll
            for (int i = 0; i < 2; i++)
                #pragma unroll
                for (int j = 0; j < 3; j++)
                    wmma::mma_sync(acc[i][j], a[i], b[j], acc[i][j]);
        }

        if (t + 1 < KTILES) {
            __half* An = As[(t + 1) & 1];
            __half* Bn = Bs[(t + 1) & 1];
            __syncthreads();
            *(H8*)(An + a_row * A_LDH + a_c0) = pack8(a_reg[0], a_reg[1]);
            #pragma unroll
            for (int i = 0; i < 3; i++)
                *(H8*)(Bn + b_row * B_LDH + b_c0 + i * 8) = pack8(b_reg[2 * i], b_reg[2 * i + 1]);
            __syncthreads();
        }
    }

    #pragma unroll
    for (int i = 0; i < 2; i++) {
        #pragma unroll
        for (int j = 0; j < 3; j++) {
            const int col   = wn + j * 16;
            const int slice = col >> 6;          // 0,1,2 -> q,k,v
            const int lcol  = col & 63;
            float* dst = (slice == 0) ? g_q : ((slice == 1) ? g_k : g_v);
            wmma::store_matrix_sync(dst + (size_t)(m_base + wm + i * 16) * HS + lcol,
                                    acc[i][j], HS, wmma::mem_row_major);
        }
    }
}

// =============================================================================
// Kernel 2: FlashAttention-style fused causal attention. 128 threads / CTA,
// grid (4, 512). Each warp owns 16 query rows. Q fragments persistent in regs;
// per 64-key tile: S in regs -> exp+sum in regs -> fp16 P a-frags -> PV mma
// into persistent O regs. Deferred normalization. One barrier per tile.
// =============================================================================
#define KV_LDH 72
#define ATT_SMEM_BYTES (4 * 64 * KV_LDH * 2)   // 36864

__global__ __launch_bounds__(128, 3)
void attn_kernel(float* __restrict__ out)
{
    extern __shared__ __half kvsm[];
    __half* Kb[2] = { kvsm,                   kvsm + 64 * KV_LDH };
    __half* Vb[2] = { kvsm + 2 * 64 * KV_LDH, kvsm + 3 * 64 * KV_LDH };

    const int tid  = threadIdx.x;
    const int w    = tid >> 5;          // warp 0..3 -> q rows w*16..+15
    const int lane = tid & 31;
    const int qt   = blockIdx.x;
    const int b    = blockIdx.y;

    const float* Qg = g_q + (size_t)b * TSEQ * HS + (size_t)qt * 64 * HS;
    const float* Kg = g_k + (size_t)b * TSEQ * HS;
    const float* Vg = g_v + (size_t)b * TSEQ * HS;
    float*       Og = out + (size_t)b * TSEQ * HS + (size_t)qt * 64 * HS;

    const float scale = rsqrtf((float)CEMB);

    H8 kh8[4], vh8[4];

    // ---- prologue: stage Q (scaled, half) into Kb[0] ----
    #pragma unroll
    for (int j = 0; j < 4; j++) {
        const int fidx = tid + j * 128;
        const int row  = fidx >> 3;
        const int c    = (fidx & 7) * 8;
        float4 f0 = *(const float4*)(Qg + row * HS + c);
        float4 f1 = *(const float4*)(Qg + row * HS + c + 4);
        f0.x *= scale; f0.y *= scale; f0.z *= scale; f0.w *= scale;
        f1.x *= scale; f1.y *= scale; f1.z *= scale; f1.w *= scale;
        *(H8*)(Kb[0] + row * KV_LDH + c) = pack8(f0, f1);
    }
    __syncthreads();

    // ---- load Q fragments (4 k-chunks x 4 regs), persistent ----
    uint32_t qf[4][4];
    {
        const uint32_t qbase = (uint32_t)__cvta_generic_to_shared(Kb[0]);
        #pragma unroll
        for (int kc = 0; kc < 4; kc++) {
            const int rrow = w * 16 + ((lane >> 3) & 1) * 8 + (lane & 7);
            const int rcol = kc * 16 + (lane >> 4) * 8;
            LDM_X4(qf[kc][0], qf[kc][1], qf[kc][2], qf[kc][3],
                   qbase + (uint32_t)(rrow * KV_LDH + rcol) * 2);
        }
    }

    // ---- load K0 / V0 ----
    #pragma unroll
    for (int j = 0; j < 4; j++) {
        const int fidx = tid + j * 128;
        const int row  = fidx >> 3;
        const int c    = (fidx & 7) * 8;
        float4 f0 = *(const float4*)(Kg + row * HS + c);
        float4 f1 = *(const float4*)(Kg + row * HS + c + 4);
        kh8[j] = pack8(f0, f1);
        float4 g0 = *(const float4*)(Vg + row * HS + c);
        float4 g1 = *(const float4*)(Vg + row * HS + c + 4);
        vh8[j] = pack8(g0, g1);
    }
    __syncthreads();   // Q fragment reads complete before overwrite
    #pragma unroll
    for (int j = 0; j < 4; j++) {
        const int fidx = tid + j * 128;
        const int row  = fidx >> 3;
        const int c    = (fidx & 7) * 8;
        *(H8*)(Kb[0] + row * KV_LDH + c) = kh8[j];
        *(H8*)(Vb[0] + row * KV_LDH + c) = vh8[j];
    }
    __syncthreads();

    float oacc[8][4];
    #pragma unroll
    for (int n = 0; n < 8; n++)
        #pragma unroll
        for (int e = 0; e < 4; e++) oacc[n][e] = 0.0f;
    float sum0 = 0.0f, sum1 = 0.0f;

    const int row0 = w * 16 + (lane >> 2);   // local q row for c0/c1; +8 for c2/c3
    const int kq   = 2 * (lane & 3);         // key sub-index within n-tile

    for (int kt = 0; kt <= qt; kt++) {
        const int cur = kt & 1;
        const bool diag = (kt == qt);
        const int ntmax = diag ? (2 * w + 2) : 8;

        if (kt < qt) {
            #pragma unroll
            for (int j = 0; j < 4; j++) {
                const int fidx = tid + j * 128;
                const int row  = fidx >> 3;
                const int c    = (fidx & 7) * 8;
                const float* kp = Kg + ((kt + 1) * 64 + row) * HS + c;
                const float* vp = Vg + ((kt + 1) * 64 + row) * HS + c;
                float4 f0 = *(const float4*)(kp);
                float4 f1 = *(const float4*)(kp + 4);
                kh8[j] = pack8(f0, f1);
                float4 g0 = *(const float4*)(vp);
                float4 g1 = *(const float4*)(vp + 4);
                vh8[j] = pack8(g0, g1);
            }
        }

        // ---- S = Q K^T for this tile (regs) ----
        const uint32_t kbase = (uint32_t)__cvta_generic_to_shared(Kb[cur]);
        float sacc[8][4];
        #pragma unroll
        for (int nt = 0; nt < 8; nt++) {
            if (nt < ntmax) {
                #pragma unroll
                for (int e = 0; e < 4; e++) sacc[nt][e] = 0.0f;
                #pragma unroll
                for (int kc = 0; kc < 4; kc++) {
                    uint32_t b0, b1;
                    const int rrow = nt * 8 + (lane & 7);
                    const int rcol = kc * 16 + ((lane >> 3) & 1) * 8;
                    LDM_X2(b0, b1, kbase + (uint32_t)(rrow * KV_LDH + rcol) * 2);
                    mma16816(sacc[nt], qf[kc][0], qf[kc][1], qf[kc][2], qf[kc][3], b0, b1);
                }
            }
        }

        // ---- exp + row sums (mask on diagonal tile) ----
        #pragma unroll
        for (int nt = 0; nt < 8; nt++) {
            if (nt < ntmax) {
                if (diag && nt >= 2 * w) {
                    const int k0 = nt * 8 + kq;
                    sacc[nt][0] = (k0     <= row0)     ? __expf(sacc[nt][0]) : 0.0f;
                    sacc[nt][1] = (k0 + 1 <= row0)     ? __expf(sacc[nt][1]) : 0.0f;
                    sacc[nt][2] = (k0     <= row0 + 8) ? __expf(sacc[nt][2]) : 0.0f;
                    sacc[nt][3] = (k0 + 1 <= row0 + 8) ? __expf(sacc[nt][3]) : 0.0f;
                } else {
                    sacc[nt][0] = __expf(sacc[nt][0]);
                    sacc[nt][1] = __expf(sacc[nt][1]);
                    sacc[nt][2] = __expf(sacc[nt][2]);
                    sacc[nt][3] = __expf(sacc[nt][3]);
                }
                sum0 += sacc[nt][0] + sacc[nt][1];
                sum1 += sacc[nt][2] + sacc[nt][3];
            }
        }

        // ---- stage next K/V tiles (other buffers; safe since last read kt-1) ----
        if (kt < qt) {
            #pragma unroll
            for (int j = 0; j < 4; j++) {
                const int fidx = tid + j * 128;
                const int row  = fidx >> 3;
                const int c    = (fidx & 7) * 8;
                *(H8*)(Kb[cur ^ 1] + row * KV_LDH + c) = kh8[j];
                *(H8*)(Vb[cur ^ 1] + row * KV_LDH + c) = vh8[j];
            }
        }

        // ---- O += P V (P packed from sacc in regs) ----
        const uint32_t vbase = (uint32_t)__cvta_generic_to_shared(Vb[cur]);
        const int kcmax = diag ? (w + 1) : 4;
        #pragma unroll
        for (int kc = 0; kc < 4; kc++) {
            if (kc < kcmax) {
                const uint32_t p0 = h2u(__floats2half2_rn(sacc[2 * kc][0],     sacc[2 * kc][1]));
                const uint32_t p1 = h2u(__floats2half2_rn(sacc[2 * kc][2],     sacc[2 * kc][3]));
                const uint32_t p2 = h2u(__floats2half2_rn(sacc[2 * kc + 1][0], sacc[2 * kc + 1][1]));
                const uint32_t p3 = h2u(__floats2half2_rn(sacc[2 * kc + 1][2], sacc[2 * kc + 1][3]));
                #pragma unroll
                for (int nt = 0; nt < 8; nt++) {
                    uint32_t b0, b1;
                    const int rrow = kc * 16 + (lane & 15);
                    LDM_X2T(b0, b1, vbase + (uint32_t)(rrow * KV_LDH + nt * 8) * 2);
                    mma16816(oacc[nt], p0, p1, p2, p3, b0, b1);
                }
            }
        }
        __syncthreads();
    }

    // ---- finalize: quad-reduce sums, normalize, store ----
    #pragma unroll
    for (int off = 1; off <= 2; off <<= 1) {
        sum0 += __shfl_xor_sync(0xffffffffu, sum0, off);
        sum1 += __shfl_xor_sync(0xffffffffu, sum1, off);
    }
    const float inv0 = 1.0f / sum0;
    const float inv1 = 1.0f / sum1;

    float* o0 = Og + (size_t)row0 * HS + kq;
    float* o1 = o0 + 8 * HS;
    #pragma unroll
    for (int nt = 0; nt < 8; nt++) {
        *(float2*)(o0 + nt * 8) = make_float2(oacc[nt][0] * inv0, oacc[nt][1] * inv0);
        *(float2*)(o1 + nt * 8) = make_float2(oacc[nt][2] * inv1, oacc[nt][3] * inv1);
    }
}

// =============================================================================
extern "C" void kernel_launch(void* const* d_in, const int* in_sizes, int n_in,
                              void* d_out, int out_size)
{
    const float* x = (const float*)d_in[0];     // [512,256,384]
    const float* w = (const float*)d_in[1];     // [384,192]
    float* out = (float*)d_out;                 // [512,256,64]

    (void)in_sizes; (void)n_in; (void)out_size;

    static bool attr_set = false;
    if (!attr_set) {
        cudaFuncSetAttribute(attn_kernel, cudaFuncAttributeMaxDynamicSharedMemorySize,
                             ATT_SMEM_BYTES);
        attr_set = true;
    }

    qkv_proj_kernel<<<MTOT / PBM, 256>>>(x, w);
    attn_kernel<<<dim3(4, BATCH), 128, ATT_SMEM_BYTES>>>(out);
}

// round 12
// speedup vs baseline: 1.2601x; 1.0428x over previous
#include <cuda_runtime.h>
#include <cuda_fp16.h>
#include <cstdint>

// Problem dims
#define BATCH 512
#define TSEQ  256
#define CEMB  384
#define HS    64
#define MTOT  (BATCH * TSEQ)   // 131072

// ---------------- scratch (device globals: allocation-guard safe) -------------
// HALF intermediates; g_q pre-scaled by 1/sqrt(384).
__device__ __half g_q[MTOT * HS];
__device__ __half g_k[MTOT * HS];
__device__ __half g_v[MTOT * HS];

struct alignas(16) H8 { __half2 h[4]; };

__device__ __forceinline__ H8 pack8(float4 a, float4 b) {
    H8 r;
    r.h[0] = __floats2half2_rn(a.x, a.y);
    r.h[1] = __floats2half2_rn(a.z, a.w);
    r.h[2] = __floats2half2_rn(b.x, b.y);
    r.h[3] = __floats2half2_rn(b.z, b.w);
    return r;
}

__device__ __forceinline__ uint32_t h2u(__half2 h) {
    return *reinterpret_cast<uint32_t*>(&h);
}

// ---------------- raw PTX: ldmatrix + mma.m16n8k16 ----------------
#define LDM_X4(r0, r1, r2, r3, a) \
    asm volatile("ldmatrix.sync.aligned.m8n8.x4.shared.b16 {%0,%1,%2,%3}, [%4];" \
                 : "=r"(r0), "=r"(r1), "=r"(r2), "=r"(r3) : "r"(a))
#define LDM_X4T(r0, r1, r2, r3, a) \
    asm volatile("ldmatrix.sync.aligned.m8n8.x4.trans.shared.b16 {%0,%1,%2,%3}, [%4];" \
                 : "=r"(r0), "=r"(r1), "=r"(r2), "=r"(r3) : "r"(a))
#define LDM_X2(r0, r1, a) \
    asm volatile("ldmatrix.sync.aligned.m8n8.x2.shared.b16 {%0,%1}, [%2];" \
                 : "=r"(r0), "=r"(r1) : "r"(a))
#define LDM_X2T(r0, r1, a) \
    asm volatile("ldmatrix.sync.aligned.m8n8.x2.trans.shared.b16 {%0,%1}, [%2];" \
                 : "=r"(r0), "=r"(r1) : "r"(a))

__device__ __forceinline__ void mma16816(float* c, uint32_t a0, uint32_t a1,
                                         uint32_t a2, uint32_t a3,
                                         uint32_t b0, uint32_t b1) {
    asm volatile(
        "mma.sync.aligned.m16n8k16.row.col.f32.f16.f16.f32 "
        "{%0,%1,%2,%3}, {%4,%5,%6,%7}, {%8,%9}, {%0,%1,%2,%3};"
        : "+f"(c[0]), "+f"(c[1]), "+f"(c[2]), "+f"(c[3])
        : "r"(a0), "r"(a1), "r"(a2), "r"(a3), "r"(b0), "r"(b1));
}

// =============================================================================
// Kernel 1: QKV projection, raw mma PTX.  qkv = x @ w  (M=131072, N=192, K=384)
// 256 threads, CTA tile 64x192, BK=32, double-buffered half smem + reg prefetch.
// 8 warps = 4 row-groups (16 rows) x 2 col-groups (96 cols = 12 n8 tiles).
// Epilogue: known m16n8 layout -> direct half2 STG (q scaled by 1/sqrt(384)).
// =============================================================================
#define PBM 64
#define PBN 192
#define PBK 32
#define A_LDH 40
#define B_LDH 200
#define KTILES (CEMB / PBK)   // 12

__global__ __launch_bounds__(256, 2)
void qkv_proj_kernel(const float* __restrict__ x, const float* __restrict__ w)
{
    __shared__ __half As[2][PBM * A_LDH];   // 10240B
    __shared__ __half Bs[2][PBK * B_LDH];   // 25600B

    const int tid    = threadIdx.x;
    const int wid    = tid >> 5;
    const int lane   = tid & 31;
    const int m_base = blockIdx.x * PBM;

    const int wr = (wid & 3) * 16;       // warp row base (0..48)
    const int wc = (wid >> 2) * 96;      // warp col base (0 or 96)

    // A staging: row = tid>>2 (0..63), c0 = (tid&3)*8 (8 floats -> 1 H8)
    const int a_row = tid >> 2;
    const int a_c0  = (tid & 3) * 8;
    // B staging: row = tid>>3 (0..31), c0 = (tid&7)*24 (24 floats -> 3 H8)
    const int b_row = tid >> 3;
    const int b_c0  = (tid & 7) * 24;

    const float* xA = x + (size_t)(m_base + a_row) * CEMB + a_c0;
    const float* wB = w + (size_t)b_row * PBN + b_c0;

    float4 a_reg[2];
    float4 b_reg[6];

    // prologue: tile 0
    #pragma unroll
    for (int i = 0; i < 2; i++) a_reg[i] = *(const float4*)(xA + i * 4);
    #pragma unroll
    for (int i = 0; i < 6; i++) b_reg[i] = *(const float4*)(wB + i * 4);

    *(H8*)(As[0] + a_row * A_LDH + a_c0) = pack8(a_reg[0], a_reg[1]);
    #pragma unroll
    for (int i = 0; i < 3; i++)
        *(H8*)(Bs[0] + b_row * B_LDH + b_c0 + i * 8) = pack8(b_reg[2 * i], b_reg[2 * i + 1]);
    __syncthreads();

    float acc[12][4];
    #pragma unroll
    for (int nt = 0; nt < 12; nt++)
        #pragma unroll
        for (int e = 0; e < 4; e++) acc[nt][e] = 0.0f;

    // ldmatrix lane-address components
    const int lrow8 = (lane & 7) + ((lane >> 3) & 1) * 8;   // 0..15
    const int lcol8 = (lane >> 4) * 8;                       // 0 or 8

    for (int t = 0; t < KTILES; t++) {
        if (t + 1 < KTILES) {
            const int k0 = (t + 1) * PBK;
            #pragma unroll
            for (int i = 0; i < 2; i++) a_reg[i] = *(const float4*)(xA + k0 + i * 4);
            const float* wn2 = wB + (size_t)k0 * PBN;
            #pragma unroll
            for (int i = 0; i < 6; i++) b_reg[i] = *(const float4*)(wn2 + i * 4);
        }

        const uint32_t abase = (uint32_t)__cvta_generic_to_shared(As[t & 1]);
        const uint32_t bbase = (uint32_t)__cvta_generic_to_shared(Bs[t & 1]);

        #pragma unroll
        for (int kk = 0; kk < PBK; kk += 16) {
            uint32_t a0, a1, a2, a3;
            LDM_X4(a0, a1, a2, a3,
                   abase + (uint32_t)((wr + lrow8) * A_LDH + kk + lcol8) * 2);
            #pragma unroll
            for (int np = 0; np < 6; np++) {
                uint32_t b0, b1, b2, b3;
                // lanes 0-15 -> rows kk..kk+15 at col nb; lanes 16-31 -> col nb+8
                LDM_X4T(b0, b1, b2, b3,
                        bbase + (uint32_t)((kk + lrow8) * B_LDH + wc + np * 16 + lcol8) * 2);
                mma16816(acc[2 * np],     a0, a1, a2, a3, b0, b1);
                mma16816(acc[2 * np + 1], a0, a1, a2, a3, b2, b3);
            }
        }

        if (t + 1 < KTILES) {
            __half* An = As[(t + 1) & 1];
            __half* Bn = Bs[(t + 1) & 1];
            __syncthreads();
            *(H8*)(An + a_row * A_LDH + a_c0) = pack8(a_reg[0], a_reg[1]);
            #pragma unroll
            for (int i = 0; i < 3; i++)
                *(H8*)(Bn + b_row * B_LDH + b_c0 + i * 8) = pack8(b_reg[2 * i], b_reg[2 * i + 1]);
            __syncthreads();
        }
    }

    // ---- epilogue: known m16n8 acc layout -> half2 stores; q scaled ----
    const float scale = rsqrtf((float)CEMB);
    const size_t row0 = (size_t)m_base + wr + (lane >> 2);
    const int    c0   = 2 * (lane & 3);
    #pragma unroll
    for (int nt = 0; nt < 12; nt++) {
        const int col   = wc + nt * 8 + c0;
        const int slice = col >> 6;          // 0,1,2 -> q,k,v
        const int lcol  = col & 63;
        __half* dst = (slice == 0) ? g_q : ((slice == 1) ? g_k : g_v);
        float f0 = acc[nt][0], f1 = acc[nt][1], f2 = acc[nt][2], f3 = acc[nt][3];
        if (slice == 0) { f0 *= scale; f1 *= scale; f2 *= scale; f3 *= scale; }
        *(__half2*)(dst + row0 * HS + lcol)       = __floats2half2_rn(f0, f1);
        *(__half2*)(dst + (row0 + 8) * HS + lcol) = __floats2half2_rn(f2, f3);
    }
}

// =============================================================================
// Kernel 2: FlashAttention-style fused causal attention (R11 structure),
// now reading HALF q/k/v (pure H8 copies, scale pre-applied upstream).
// 128 threads / CTA, grid (4, 512); warp owns 16 query rows; S/P in registers.
// =============================================================================
#define KV_LDH 72
#define ATT_SMEM_BYTES (4 * 64 * KV_LDH * 2)   // 36864

__global__ __launch_bounds__(128, 3)
void attn_kernel(float* __restrict__ out)
{
    extern __shared__ __half kvsm[];
    __half* Kb[2] = { kvsm,                   kvsm + 64 * KV_LDH };
    __half* Vb[2] = { kvsm + 2 * 64 * KV_LDH, kvsm + 3 * 64 * KV_LDH };

    const int tid  = threadIdx.x;
    const int w    = tid >> 5;          // warp 0..3 -> q rows w*16..+15
    const int lane = tid & 31;
    const int qt   = blockIdx.x;
    const int b    = blockIdx.y;

    const __half* Qg = g_q + (size_t)b * TSEQ * HS + (size_t)qt * 64 * HS;
    const __half* Kg = g_k + (size_t)b * TSEQ * HS;
    const __half* Vg = g_v + (size_t)b * TSEQ * HS;
    float*        Og = out + (size_t)b * TSEQ * HS + (size_t)qt * 64 * HS;

    H8 kh8[4], vh8[4];

    // ---- prologue: stage Q (half, pre-scaled) into Kb[0] ----
    #pragma unroll
    for (int j = 0; j < 4; j++) {
        const int fidx = tid + j * 128;
        const int row  = fidx >> 3;
        const int c    = (fidx & 7) * 8;
        *(H8*)(Kb[0] + row * KV_LDH + c) = *(const H8*)(Qg + row * HS + c);
    }
    __syncthreads();

    // ---- load Q fragments (4 k-chunks x 4 regs), persistent ----
    uint32_t qf[4][4];
    {
        const uint32_t qbase = (uint32_t)__cvta_generic_to_shared(Kb[0]);
        #pragma unroll
        for (int kc = 0; kc < 4; kc++) {
            const int rrow = w * 16 + ((lane >> 3) & 1) * 8 + (lane & 7);
            const int rcol = kc * 16 + (lane >> 4) * 8;
            LDM_X4(qf[kc][0], qf[kc][1], qf[kc][2], qf[kc][3],
                   qbase + (uint32_t)(rrow * KV_LDH + rcol) * 2);
        }
    }

    // ---- load K0 / V0 ----
    #pragma unroll
    for (int j = 0; j < 4; j++) {
        const int fidx = tid + j * 128;
        const int row  = fidx >> 3;
        const int c    = (fidx & 7) * 8;
        kh8[j] = *(const H8*)(Kg + row * HS + c);
        vh8[j] = *(const H8*)(Vg + row * HS + c);
    }
    __syncthreads();   // Q fragment reads complete before overwrite
    #pragma unroll
    for (int j = 0; j < 4; j++) {
        const int fidx = tid + j * 128;
        const int row  = fidx >> 3;
        const int c    = (fidx & 7) * 8;
        *(H8*)(Kb[0] + row * KV_LDH + c) = kh8[j];
        *(H8*)(Vb[0] + row * KV_LDH + c) = vh8[j];
    }
    __syncthreads();

    float oacc[8][4];
    #pragma unroll
    for (int n = 0; n < 8; n++)
        #pragma unroll
        for (int e = 0; e < 4; e++) oacc[n][e] = 0.0f;
    float sum0 = 0.0f, sum1 = 0.0f;

    const int row0 = w * 16 + (lane >> 2);   // local q row for c0/c1; +8 for c2/c3
    const int kq   = 2 * (lane & 3);         // key sub-index within n-tile

    for (int kt = 0; kt <= qt; kt++) {
        const int cur = kt & 1;
        const bool diag = (kt == qt);
        const int ntmax = diag ? (2 * w + 2) : 8;

        if (kt < qt) {
            #pragma unroll
            for (int j = 0; j < 4; j++) {
                const int fidx = tid + j * 128;
                const int row  = (kt + 1) * 64 + (fidx >> 3);
                const int c    = (fidx & 7) * 8;
                kh8[j] = *(const H8*)(Kg + row * HS + c);
                vh8[j] = *(const H8*)(Vg + row * HS + c);
            }
        }

        // ---- S = Q K^T for this tile (regs) ----
        const uint32_t kbase = (uint32_t)__cvta_generic_to_shared(Kb[cur]);
        float sacc[8][4];
        #pragma unroll
        for (int nt = 0; nt < 8; nt++) {
            if (nt < ntmax) {
                #pragma unroll
                for (int e = 0; e < 4; e++) sacc[nt][e] = 0.0f;
                #pragma unroll
                for (int kc = 0; kc < 4; kc++) {
                    uint32_t b0, b1;
                    const int rrow = nt * 8 + (lane & 7);
                    const int rcol = kc * 16 + ((lane >> 3) & 1) * 8;
                    LDM_X2(b0, b1, kbase + (uint32_t)(rrow * KV_LDH + rcol) * 2);
                    mma16816(sacc[nt], qf[kc][0], qf[kc][1], qf[kc][2], qf[kc][3], b0, b1);
                }
            }
        }

        // ---- exp + row sums (mask on diagonal tile) ----
        #pragma unroll
        for (int nt = 0; nt < 8; nt++) {
            if (nt < ntmax) {
                if (diag && nt >= 2 * w) {
                    const int k0 = nt * 8 + kq;
                    sacc[nt][0] = (k0     <= row0)     ? __expf(sacc[nt][0]) : 0.0f;
                    sacc[nt][1] = (k0 + 1 <= row0)     ? __expf(sacc[nt][1]) : 0.0f;
                    sacc[nt][2] = (k0     <= row0 + 8) ? __expf(sacc[nt][2]) : 0.0f;
                    sacc[nt][3] = (k0 + 1 <= row0 + 8) ? __expf(sacc[nt][3]) : 0.0f;
                } else {
                    sacc[nt][0] = __expf(sacc[nt][0]);
                    sacc[nt][1] = __expf(sacc[nt][1]);
                    sacc[nt][2] = __expf(sacc[nt][2]);
                    sacc[nt][3] = __expf(sacc[nt][3]);
                }
                sum0 += sacc[nt][0] + sacc[nt][1];
                sum1 += sacc[nt][2] + sacc[nt][3];
            }
        }

        // ---- stage next K/V tiles (other buffers; safe since last read kt-1) ----
        if (kt < qt) {
            #pragma unroll
            for (int j = 0; j < 4; j++) {
                const int fidx = tid + j * 128;
                const int row  = fidx >> 3;
                const int c    = (fidx & 7) * 8;
                *(H8*)(Kb[cur ^ 1] + row * KV_LDH + c) = kh8[j];
                *(H8*)(Vb[cur ^ 1] + row * KV_LDH + c) = vh8[j];
            }
        }

        // ---- O += P V (P packed from sacc in regs) ----
        const uint32_t vbase = (uint32_t)__cvta_generic_to_shared(Vb[cur]);
        const int kcmax = diag ? (w + 1) : 4;
        #pragma unroll
        for (int kc = 0; kc < 4; kc++) {
            if (kc < kcmax) {
                const uint32_t p0 = h2u(__floats2half2_rn(sacc[2 * kc][0],     sacc[2 * kc][1]));
                const uint32_t p1 = h2u(__floats2half2_rn(sacc[2 * kc][2],     sacc[2 * kc][3]));
                const uint32_t p2 = h2u(__floats2half2_rn(sacc[2 * kc + 1][0], sacc[2 * kc + 1][1]));
                const uint32_t p3 = h2u(__floats2half2_rn(sacc[2 * kc + 1][2], sacc[2 * kc + 1][3]));
                #pragma unroll
                for (int nt = 0; nt < 8; nt++) {
                    uint32_t b0, b1;
                    const int rrow = kc * 16 + (lane & 15);
                    LDM_X2T(b0, b1, vbase + (uint32_t)(rrow * KV_LDH + nt * 8) * 2);
                    mma16816(oacc[nt], p0, p1, p2, p3, b0, b1);
                }
            }
        }
        __syncthreads();
    }

    // ---- finalize: quad-reduce sums, normalize, store ----
    #pragma unroll
    for (int off = 1; off <= 2; off <<= 1) {
        sum0 += __shfl_xor_sync(0xffffffffu, sum0, off);
        sum1 += __shfl_xor_sync(0xffffffffu, sum1, off);
    }
    const float inv0 = 1.0f / sum0;
    const float inv1 = 1.0f / sum1;

    float* o0 = Og + (size_t)row0 * HS + kq;
    float* o1 = o0 + 8 * HS;
    #pragma unroll
    for (int nt = 0; nt < 8; nt++) {
        *(float2*)(o0 + nt * 8) = make_float2(oacc[nt][0] * inv0, oacc[nt][1] * inv0);
        *(float2*)(o1 + nt * 8) = make_float2(oacc[nt][2] * inv1, oacc[nt][3] * inv1);
    }
}

// =============================================================================
extern "C" void kernel_launch(void* const* d_in, const int* in_sizes, int n_in,
                              void* d_out, int out_size)
{
    const float* x = (const float*)d_in[0];     // [512,256,384]
    const float* w = (const float*)d_in[1];     // [384,192]
    float* out = (float*)d_out;                 // [512,256,64]

    (void)in_sizes; (void)n_in; (void)out_size;

    static bool attr_set = false;
    if (!attr_set) {
        cudaFuncSetAttribute(attn_kernel, cudaFuncAttributeMaxDynamicSharedMemorySize,
                             ATT_SMEM_BYTES);
        attr_set = true;
    }

    qkv_proj_kernel<<<MTOT / PBM, 256>>>(x, w);
    attn_kernel<<<dim3(4, BATCH), 128, ATT_SMEM_BYTES>>>(out);
}